// round 12
// baseline (speedup 1.0000x reference)
#include <cuda_runtime.h>
#include <cuda_fp16.h>
#include <cstdint>

// ---------------------------------------------------------------------------
// Problem constants
// ---------------------------------------------------------------------------
#define SEQ_LEN   2048
#define BATCH     16
#define HID       1024
#define N3        3072
#define KDIM      1024
#define MROWS     32768
#define SBH       (SEQ_LEN * BATCH * HID)  // 33554432

// Scratch (device globals; no runtime allocation allowed)
__device__ __half g_U[(size_t)MROWS * N3];    // GEMM output [M, 3H], fp16
__device__ __half g_A[(size_t)MROWS * KDIM];  // input fp16 [M,K] (= X in fp16)
__device__ __half g_B[(size_t)N3 * KDIM];     // weight^T fp16 [N,K]

// ---------------------------------------------------------------------------
// PTX helpers
// ---------------------------------------------------------------------------
__device__ __forceinline__ uint32_t smem_u32(const void* p) {
    uint32_t a;
    asm("{ .reg .u64 t; cvta.to.shared.u64 t, %1; cvt.u32.u64 %0, t; }"
        : "=r"(a) : "l"(p));
    return a;
}

__device__ __forceinline__ void cpasync16(uint32_t dst, const void* src) {
    asm volatile("cp.async.cg.shared.global [%0], [%1], 16;"
        :: "r"(dst), "l"(src) : "memory");
}

__device__ __forceinline__ void ldsm_x4(uint32_t r[4], uint32_t addr) {
    asm volatile("ldmatrix.sync.aligned.m8n8.x4.shared.b16 {%0,%1,%2,%3}, [%4];"
        : "=r"(r[0]), "=r"(r[1]), "=r"(r[2]), "=r"(r[3]) : "r"(addr));
}

__device__ __forceinline__ void mma16816(float* c, const uint32_t* a,
                                         uint32_t b0, uint32_t b1) {
    asm volatile(
        "mma.sync.aligned.m16n8k16.row.col.f32.f16.f16.f32 "
        "{%0,%1,%2,%3}, {%4,%5,%6,%7}, {%8,%9}, {%0,%1,%2,%3};"
        : "+f"(c[0]), "+f"(c[1]), "+f"(c[2]), "+f"(c[3])
        : "r"(a[0]), "r"(a[1]), "r"(a[2]), "r"(a[3]), "r"(b0), "r"(b1));
}

__device__ __forceinline__ float tanh_fast(float x) {
    float y;
    asm("tanh.approx.f32 %0, %1;" : "=f"(y) : "f"(x));
    return y;
}

// ---------------------------------------------------------------------------
// Conversion kernels
// ---------------------------------------------------------------------------
__global__ void __launch_bounds__(256) convA(
    const float4* __restrict__ X, __half2* __restrict__ A2)
{
    size_t i = (size_t)blockIdx.x * blockDim.x + threadIdx.x;
    float4 v = X[i];
    A2[2 * i]     = __floats2half2_rn(v.x, v.y);
    A2[2 * i + 1] = __floats2half2_rn(v.z, v.w);
}

// Transpose weight [K,N3] -> [N3,K], fp16
__global__ void __launch_bounds__(1024) convW(
    const float* __restrict__ W, __half* __restrict__ B)
{
    __shared__ float t[32][33];
    int n0 = blockIdx.x * 32, k0 = blockIdx.y * 32;
    int tx = threadIdx.x, ty = threadIdx.y;
    t[ty][tx] = W[(size_t)(k0 + ty) * N3 + n0 + tx];
    __syncthreads();
    B[(size_t)(n0 + ty) * KDIM + k0 + tx] = __float2half_rn(t[tx][ty]);
}

// ---------------------------------------------------------------------------
// fp16 GEMM via mma.sync: U(fp16) = A*B^T (fp32 acc)
// CTA tile 128x128, 4 warps of 64x64 (128 threads), 2 CTAs/SM.
// K-chunk 64, SW128 smem, 3-stage single-sync ring.
// NEW: ks-level fragment double-buffering — load ks+1 frags before ks MMAs
// (256 regs/thread available at this occupancy; LDS latency hidden).
// ---------------------------------------------------------------------------
#define TKC 64
#define NCHUNK (KDIM / TKC)          // 16
#define TILE_BYTES 16384             // 128 rows x 128B
#define STAGE_BYTES (2 * TILE_BYTES) // A + B = 32KB
#define NSTAGE 3
#define GEMM_SMEM (1024 + NSTAGE * STAGE_BYTES)

__global__ void __launch_bounds__(128, 2) gemm_fp16(
    const __half* __restrict__ A, const __half* __restrict__ B,
    __half* __restrict__ U)
{
    extern __shared__ char dsm[];
    const uint32_t base = (smem_u32(dsm) + 1023) & ~1023u;

    const int tid = threadIdx.x;
    const int wid = tid >> 5, lid = tid & 31;
    const int m0 = blockIdx.y * 128;
    const int n0 = blockIdx.x * 128;
    const int wm = (wid & 1) * 64;     // warp M offset (0 or 64)
    const int wn = (wid >> 1) * 64;    // warp N offset (0 or 64)

    // loader: 128 threads cover A (8 chunks) + B (8 chunks) of 16B each
    auto load_chunk = [&](int j, int s) {
        const uint32_t sb = base + s * STAGE_BYTES;
        const int koff = j * TKC;
#pragma unroll
        for (int i = 0; i < 8; i++) {
            int q = i * 128 + tid;
            int r = q >> 3, c = q & 7;
            uint32_t sw = (uint32_t)(r * 128 + ((c * 16) ^ ((r & 7) << 4)));
            cpasync16(sb + sw,              A + (size_t)(m0 + r) * KDIM + koff + c * 8);
            cpasync16(sb + TILE_BYTES + sw, B + (size_t)(n0 + r) * KDIM + koff + c * 8);
        }
        asm volatile("cp.async.commit_group;" ::: "memory");
    };

    const int fr = lid & 15;
    const int fc = lid >> 4;
    const uint32_t axor = (uint32_t)((fr & 7) << 4);

    float acc[4][8][4];
#pragma unroll
    for (int a = 0; a < 4; a++)
#pragma unroll
        for (int b = 0; b < 8; b++)
#pragma unroll
            for (int q = 0; q < 4; q++) acc[a][b][q] = 0.0f;

    load_chunk(0, 0);
    load_chunk(1, 1);

    // double-buffered fragments
    uint32_t afr[2][4][4], bfr[2][4][4];

    for (int j = 0; j < NCHUNK; j++) {
        const int s = j % NSTAGE;
        if (j + 1 < NCHUNK) asm volatile("cp.async.wait_group 1;" ::: "memory");
        else                asm volatile("cp.async.wait_group 0;" ::: "memory");
        __syncthreads();
        // stage (j+2)%3 == (j-1)%3 was consumed at iter j-1; the sync above
        // makes that consumption block-wide complete before we overwrite it.
        if (j + 2 < NCHUNK) load_chunk(j + 2, (j + 2) % NSTAGE);

        const uint32_t As = base + s * STAGE_BYTES;
        const uint32_t Bs = As + TILE_BYTES;

        auto ld_frags = [&](int ks, uint32_t af[4][4], uint32_t bf[4][4]) {
            const uint32_t kb = (uint32_t)(ks * 32 + fc * 16) ^ axor;
#pragma unroll
            for (int mi = 0; mi < 4; mi++)
                ldsm_x4(af[mi], As + (uint32_t)((wm + mi * 16 + fr) * 128) + kb);
#pragma unroll
            for (int nj = 0; nj < 4; nj++)
                ldsm_x4(bf[nj], Bs + (uint32_t)((wn + nj * 16 + fr) * 128) + kb);
        };

        ld_frags(0, afr[0], bfr[0]);
#pragma unroll
        for (int ks = 0; ks < 4; ks++) {
            const int cur = ks & 1, nxt = cur ^ 1;
            if (ks < 3) ld_frags(ks + 1, afr[nxt], bfr[nxt]);
#pragma unroll
            for (int mi = 0; mi < 4; mi++)
#pragma unroll
                for (int n8 = 0; n8 < 8; n8++)
                    mma16816(acc[mi][n8], afr[cur][mi],
                             bfr[cur][n8 >> 1][n8 & 1],
                             bfr[cur][n8 >> 1][(n8 & 1) + 2]);
        }
    }

    // epilogue: fp32 acc -> fp16 U
    const int crow = lid >> 2;
    const int ccol = (lid & 3) * 2;
#pragma unroll
    for (int mi = 0; mi < 4; mi++) {
#pragma unroll
        for (int n8 = 0; n8 < 8; n8++) {
            __half* p0 = U + (size_t)(m0 + wm + mi * 16 + crow) * N3
                           + n0 + wn + n8 * 8 + ccol;
            __half* p1 = p0 + (size_t)8 * N3;
            *(__half2*)p0 = __floats2half2_rn(acc[mi][n8][0], acc[mi][n8][1]);
            *(__half2*)p1 = __floats2half2_rn(acc[mi][n8][2], acc[mi][n8][3]);
        }
    }
}

// ---------------------------------------------------------------------------
// SRU scan with cp.async smem staging + tanh.approx gates.
// Block = 128 threads = 128 h-chains; groups of 64 timesteps (halved
// barrier count vs SGS=32), 3-stage ring (196KB smem).
// ---------------------------------------------------------------------------
#define SGS 64
#define GRP_U (SGS * 768)            // 49152
#define GRP_X (SGS * 256)            // 16384
#define GRP_BYTES (GRP_U + GRP_X)    // 65536
#define NGR (SEQ_LEN / SGS)          // 32
#define SSTG 3
#define SCAN_SMEM (SSTG * GRP_BYTES) // 196608

__global__ void __launch_bounds__(128) sru_scan(
    const __half* __restrict__ Uh, const __half* __restrict__ Xh,
    const float* __restrict__ bias,
    float* __restrict__ Hout, float* __restrict__ Cout)
{
    extern __shared__ char ssm[];
    const uint32_t sbase = smem_u32(ssm);
    const int tid = threadIdx.x;
    const int b   = blockIdx.x >> 3;
    const int hb  = blockIdx.x & 7;
    const int h   = hb * 128 + tid;

    const float b0 = bias[h];
    const float b1 = bias[HID + h];
    const float hb0 = 0.5f * b0;   // gate arg scaled by 1/2 for tanh identity
    const float hb1 = 0.5f * b1;

    // loader chunk geometry: U 24 chunks, X 8 chunks of 16B per thread
    int us[24], uc[24], xs[8], xc[8];
#pragma unroll
    for (int k = 0; k < 24; k++) { int q = tid + 128 * k; us[k] = q / 48; uc[k] = q % 48; }
#pragma unroll
    for (int k = 0; k < 8; k++)  { int q = tid + 128 * k; xs[k] = q >> 4; xc[k] = q & 15; }

    const size_t UT = (size_t)BATCH * N3;    // halves per timestep in U
    const size_t XT = (size_t)BATCH * HID;   // elems per timestep in X / outputs

    const __half* Ublk = Uh + (size_t)b * N3 + hb * 384;
    const __half* Xblk = Xh + (size_t)b * HID + hb * 128;

    auto load_group = [&](int g, int s) {
        const uint32_t sb = sbase + s * GRP_BYTES;
        const __half* Ug = Ublk + (size_t)g * SGS * UT;
        const __half* Xg = Xblk + (size_t)g * SGS * XT;
#pragma unroll
        for (int k = 0; k < 24; k++)
            cpasync16(sb + us[k] * 768 + uc[k] * 16,
                      Ug + (size_t)us[k] * UT + uc[k] * 8);
#pragma unroll
        for (int k = 0; k < 8; k++)
            cpasync16(sb + GRP_U + xs[k] * 256 + xc[k] * 16,
                      Xg + (size_t)xs[k] * XT + xc[k] * 8);
        asm volatile("cp.async.commit_group;" ::: "memory");
    };

    load_group(0, 0);
    load_group(1, 1);

    float c = 0.0f;
    float* hp = Hout + (size_t)b * HID + h;
    float* cp = Cout + (size_t)b * HID + h;

    for (int g = 0; g < NGR; g++) {
        const int s = g % SSTG;
        if (g + 1 < NGR) asm volatile("cp.async.wait_group 1;" ::: "memory");
        else             asm volatile("cp.async.wait_group 0;" ::: "memory");
        __syncthreads();
        if (g + 2 < NGR) load_group(g + 2, (g + 2) % SSTG);

        const char* ub = ssm + s * GRP_BYTES;
        const char* xb = ub + GRP_U;
#pragma unroll 8
        for (int i = 0; i < SGS; i++) {
            const __half* up = (const __half*)(ub + i * 768) + 3 * tid;
            // half of (u + bias): gate = sigmoid(2*(hu + hb*c)) via tanh
            float hu0 = fmaf(0.5f, __half2float(up[0]), hb0);
            float hu1 = fmaf(0.5f, __half2float(up[1]), hb1);
            float u2  = __half2float(up[2]);
            float xv  = __half2float(*((const __half*)(xb + i * 256) + tid));

            // c' = u2 + f*(c-u2),  f = 0.5*th_f + 0.5
            float th_f = tanh_fast(fmaf(hb0, c, hu0));
            float d    = fmaf(0.5f, c, -0.5f * u2);
            c = fmaf(th_f, d, u2 + d);

            // h = x + r*(c'-x), r = 0.5*th_r + 0.5  (th_r from pre-update c)
            float th_r = tanh_fast(fmaf(hb1, d + d + u2, hu1)); // d+d+u2 == old c
            float e    = fmaf(0.5f, c, -0.5f * xv);
            float hv   = fmaf(th_r, e, xv + e);

            const size_t off = (size_t)(g * SGS + i) * XT;
            __stcs(hp + off, hv);
            __stcs(cp + off, c);
        }
    }
}

// ---------------------------------------------------------------------------
// Launch
// ---------------------------------------------------------------------------
extern "C" void kernel_launch(void* const* d_in, const int* in_sizes, int n_in,
                              void* d_out, int out_size)
{
    const float* input  = (const float*)d_in[0]; // [2048,16,1024]
    const float* weight = (const float*)d_in[1]; // [1024,3072]
    const float* bias   = (const float*)d_in[2]; // [2048]
    // d_in[3] = v, intentionally unused (source quirk)

    float* Hout = (float*)d_out;
    float* Cout = (float*)d_out + SBH;

    __half *U, *A, *B;
    cudaGetSymbolAddress((void**)&U, g_U);
    cudaGetSymbolAddress((void**)&A, g_A);
    cudaGetSymbolAddress((void**)&B, g_B);

    cudaFuncSetAttribute(gemm_fp16,
                         cudaFuncAttributeMaxDynamicSharedMemorySize, GEMM_SMEM);
    cudaFuncSetAttribute(sru_scan,
                         cudaFuncAttributeMaxDynamicSharedMemorySize, SCAN_SMEM);

    convA<<<SBH / 4 / 256, 256>>>((const float4*)input, (__half2*)A);
    convW<<<dim3(N3 / 32, KDIM / 32), dim3(32, 32)>>>(weight, B);

    gemm_fp16<<<dim3(N3 / 128, MROWS / 128), 128, GEMM_SMEM>>>(A, B, U);

    sru_scan<<<128, 128, SCAN_SMEM>>>(U, A, bias, Hout, Cout);
}

// round 13
// speedup vs baseline: 1.0011x; 1.0011x over previous
#include <cuda_runtime.h>
#include <cuda_fp16.h>
#include <cstdint>

// ---------------------------------------------------------------------------
// Problem constants
// ---------------------------------------------------------------------------
#define SEQ_LEN   2048
#define BATCH     16
#define HID       1024
#define N3        3072
#define KDIM      1024
#define MROWS     32768
#define SBH       (SEQ_LEN * BATCH * HID)  // 33554432

// Scratch (device globals; no runtime allocation allowed)
__device__ __half g_U[(size_t)MROWS * N3];    // GEMM output [M, 3H], fp16
__device__ __half g_A[(size_t)MROWS * KDIM];  // input fp16 [M,K] (= X in fp16)
__device__ __half g_B[(size_t)N3 * KDIM];     // weight^T fp16 [N,K]

// ---------------------------------------------------------------------------
// PTX helpers
// ---------------------------------------------------------------------------
__device__ __forceinline__ uint32_t smem_u32(const void* p) {
    uint32_t a;
    asm("{ .reg .u64 t; cvta.to.shared.u64 t, %1; cvt.u32.u64 %0, t; }"
        : "=r"(a) : "l"(p));
    return a;
}

__device__ __forceinline__ void cpasync16(uint32_t dst, const void* src) {
    asm volatile("cp.async.cg.shared.global [%0], [%1], 16;"
        :: "r"(dst), "l"(src) : "memory");
}

__device__ __forceinline__ void ldsm_x4(uint32_t r[4], uint32_t addr) {
    asm volatile("ldmatrix.sync.aligned.m8n8.x4.shared.b16 {%0,%1,%2,%3}, [%4];"
        : "=r"(r[0]), "=r"(r[1]), "=r"(r[2]), "=r"(r[3]) : "r"(addr));
}

__device__ __forceinline__ void mma16816(float* c, const uint32_t* a,
                                         uint32_t b0, uint32_t b1) {
    asm volatile(
        "mma.sync.aligned.m16n8k16.row.col.f32.f16.f16.f32 "
        "{%0,%1,%2,%3}, {%4,%5,%6,%7}, {%8,%9}, {%0,%1,%2,%3};"
        : "+f"(c[0]), "+f"(c[1]), "+f"(c[2]), "+f"(c[3])
        : "r"(a[0]), "r"(a[1]), "r"(a[2]), "r"(a[3]), "r"(b0), "r"(b1));
}

__device__ __forceinline__ float tanh_fast(float x) {
    float y;
    asm("tanh.approx.f32 %0, %1;" : "=f"(y) : "f"(x));
    return y;
}

__device__ __forceinline__ void stcs_half2(__half* p, __half2 v) {
    asm volatile("st.global.cs.b32 [%0], %1;" :: "l"(p), "r"(*(uint32_t*)&v) : "memory");
}

// ---------------------------------------------------------------------------
// Conversion kernels
// ---------------------------------------------------------------------------
__global__ void __launch_bounds__(256) convA(
    const float4* __restrict__ X, __half2* __restrict__ A2)
{
    size_t i = (size_t)blockIdx.x * blockDim.x + threadIdx.x;
    float4 v = X[i];
    A2[2 * i]     = __floats2half2_rn(v.x, v.y);
    A2[2 * i + 1] = __floats2half2_rn(v.z, v.w);
}

// Transpose weight [K,N3] -> [N3,K], fp16
__global__ void __launch_bounds__(1024) convW(
    const float* __restrict__ W, __half* __restrict__ B)
{
    __shared__ float t[32][33];
    int n0 = blockIdx.x * 32, k0 = blockIdx.y * 32;
    int tx = threadIdx.x, ty = threadIdx.y;
    t[ty][tx] = W[(size_t)(k0 + ty) * N3 + n0 + tx];
    __syncthreads();
    B[(size_t)(n0 + ty) * KDIM + k0 + tx] = __float2half_rn(t[tx][ty]);
}

// ---------------------------------------------------------------------------
// fp16 GEMM via mma.sync: U(fp16) = A*B^T (fp32 acc)  [R11 config, known-good]
// CTA tile 128x128, 4 warps of 64x64 (128 threads), 2 CTAs/SM.
// K-chunk 64, SW128 smem, 3-stage single-sync ring.
// Epilogue uses streaming stores (U consumed once, from DRAM, by the scan).
// ---------------------------------------------------------------------------
#define TKC 64
#define NCHUNK (KDIM / TKC)          // 16
#define TILE_BYTES 16384             // 128 rows x 128B
#define STAGE_BYTES (2 * TILE_BYTES) // A + B = 32KB
#define NSTAGE 3
#define GEMM_SMEM (1024 + NSTAGE * STAGE_BYTES)

__global__ void __launch_bounds__(128, 2) gemm_fp16(
    const __half* __restrict__ A, const __half* __restrict__ B,
    __half* __restrict__ U)
{
    extern __shared__ char dsm[];
    const uint32_t base = (smem_u32(dsm) + 1023) & ~1023u;

    const int tid = threadIdx.x;
    const int wid = tid >> 5, lid = tid & 31;
    const int m0 = blockIdx.y * 128;
    const int n0 = blockIdx.x * 128;
    const int wm = (wid & 1) * 64;     // warp M offset (0 or 64)
    const int wn = (wid >> 1) * 64;    // warp N offset (0 or 64)

    // loader: 128 threads cover A (8 chunks) + B (8 chunks) of 16B each
    auto load_chunk = [&](int j, int s) {
        const uint32_t sb = base + s * STAGE_BYTES;
        const int koff = j * TKC;
#pragma unroll
        for (int i = 0; i < 8; i++) {
            int q = i * 128 + tid;
            int r = q >> 3, c = q & 7;
            uint32_t sw = (uint32_t)(r * 128 + ((c * 16) ^ ((r & 7) << 4)));
            cpasync16(sb + sw,              A + (size_t)(m0 + r) * KDIM + koff + c * 8);
            cpasync16(sb + TILE_BYTES + sw, B + (size_t)(n0 + r) * KDIM + koff + c * 8);
        }
        asm volatile("cp.async.commit_group;" ::: "memory");
    };

    const int fr = lid & 15;
    const int fc = lid >> 4;
    const uint32_t axor = (uint32_t)((fr & 7) << 4);

    float acc[4][8][4];
#pragma unroll
    for (int a = 0; a < 4; a++)
#pragma unroll
        for (int b = 0; b < 8; b++)
#pragma unroll
            for (int q = 0; q < 4; q++) acc[a][b][q] = 0.0f;

    load_chunk(0, 0);
    load_chunk(1, 1);

    for (int j = 0; j < NCHUNK; j++) {
        const int s = j % NSTAGE;
        if (j + 1 < NCHUNK) asm volatile("cp.async.wait_group 1;" ::: "memory");
        else                asm volatile("cp.async.wait_group 0;" ::: "memory");
        __syncthreads();
        // stage (j+2)%3 == (j-1)%3 was consumed at iter j-1; the sync above
        // makes that consumption block-wide complete before we overwrite it.
        if (j + 2 < NCHUNK) load_chunk(j + 2, (j + 2) % NSTAGE);

        const uint32_t As = base + s * STAGE_BYTES;
        const uint32_t Bs = As + TILE_BYTES;

#pragma unroll
        for (int ks = 0; ks < 4; ks++) {
            const uint32_t kb = (uint32_t)(ks * 32 + fc * 16) ^ axor;

            uint32_t afr[4][4];
#pragma unroll
            for (int mi = 0; mi < 4; mi++)
                ldsm_x4(afr[mi], As + (uint32_t)((wm + mi * 16 + fr) * 128) + kb);

            uint32_t bfr[4][4];
#pragma unroll
            for (int nj = 0; nj < 4; nj++)
                ldsm_x4(bfr[nj], Bs + (uint32_t)((wn + nj * 16 + fr) * 128) + kb);

#pragma unroll
            for (int mi = 0; mi < 4; mi++)
#pragma unroll
                for (int n8 = 0; n8 < 8; n8++)
                    mma16816(acc[mi][n8], afr[mi],
                             bfr[n8 >> 1][n8 & 1], bfr[n8 >> 1][(n8 & 1) + 2]);
        }
    }

    // epilogue: fp32 acc -> fp16 U, streaming stores
    const int crow = lid >> 2;
    const int ccol = (lid & 3) * 2;
#pragma unroll
    for (int mi = 0; mi < 4; mi++) {
#pragma unroll
        for (int n8 = 0; n8 < 8; n8++) {
            __half* p0 = U + (size_t)(m0 + wm + mi * 16 + crow) * N3
                           + n0 + wn + n8 * 8 + ccol;
            __half* p1 = p0 + (size_t)8 * N3;
            stcs_half2(p0, __floats2half2_rn(acc[mi][n8][0], acc[mi][n8][1]));
            stcs_half2(p1, __floats2half2_rn(acc[mi][n8][2], acc[mi][n8][3]));
        }
    }
}

// ---------------------------------------------------------------------------
// SRU scan with cp.async smem staging + tanh.approx gates.
// NEW: 64-thread blocks, 256 blocks (2 blocks/SM, one full wave) — doubles
// block-level DRAM parallelism vs the 128-thread/128-block config.
// Groups of 32 timesteps: U 384B/step + X 128B/step = 16KB/group, 4-stage ring.
// ---------------------------------------------------------------------------
#define SGS 32
#define CH  64                         // chains per block
#define GRP_U (SGS * CH * 6)           // 12288
#define GRP_X (SGS * CH * 2)           // 4096
#define GRP_BYTES (GRP_U + GRP_X)      // 16384
#define NGR (SEQ_LEN / SGS)            // 64
#define SSTG 4
#define SCAN_SMEM (SSTG * GRP_BYTES)   // 65536

__global__ void __launch_bounds__(CH) sru_scan(
    const __half* __restrict__ Uh, const __half* __restrict__ Xh,
    const float* __restrict__ bias,
    float* __restrict__ Hout, float* __restrict__ Cout)
{
    extern __shared__ char ssm[];
    const uint32_t sbase = smem_u32(ssm);
    const int tid = threadIdx.x;                 // 0..63
    const int b   = blockIdx.x >> 4;             // 16 batches
    const int hb  = blockIdx.x & 15;             // 16 slabs of 64 h
    const int h   = hb * CH + tid;

    const float b0 = bias[h];
    const float b1 = bias[HID + h];
    const float hb0 = 0.5f * b0;   // gate arg scaled by 1/2 for tanh identity
    const float hb1 = 0.5f * b1;

    // loader chunk geometry: U 12 chunks (rows of 24x16B), X 4 chunks (rows of 8x16B)
    int us[12], uc[12], xs[4], xc[4];
#pragma unroll
    for (int k = 0; k < 12; k++) { int q = tid + CH * k; us[k] = q / 24; uc[k] = q % 24; }
#pragma unroll
    for (int k = 0; k < 4; k++)  { int q = tid + CH * k; xs[k] = q >> 3; xc[k] = q & 7; }

    const size_t UT = (size_t)BATCH * N3;    // halves per timestep in U
    const size_t XT = (size_t)BATCH * HID;   // elems per timestep in X / outputs

    const __half* Ublk = Uh + (size_t)b * N3 + hb * (CH * 3);
    const __half* Xblk = Xh + (size_t)b * HID + hb * CH;

    auto load_group = [&](int g, int s) {
        const uint32_t sb = sbase + s * GRP_BYTES;
        const __half* Ug = Ublk + (size_t)g * SGS * UT;
        const __half* Xg = Xblk + (size_t)g * SGS * XT;
#pragma unroll
        for (int k = 0; k < 12; k++)
            cpasync16(sb + us[k] * 384 + uc[k] * 16,
                      Ug + (size_t)us[k] * UT + uc[k] * 8);
#pragma unroll
        for (int k = 0; k < 4; k++)
            cpasync16(sb + GRP_U + xs[k] * 128 + xc[k] * 16,
                      Xg + (size_t)xs[k] * XT + xc[k] * 8);
        asm volatile("cp.async.commit_group;" ::: "memory");
    };

    load_group(0, 0);
    load_group(1, 1);
    load_group(2, 2);

    float c = 0.0f;
    float* hp = Hout + (size_t)b * HID + h;
    float* cp = Cout + (size_t)b * HID + h;

    for (int g = 0; g < NGR; g++) {
        const int s = g % SSTG;
        if (g + 2 < NGR)      asm volatile("cp.async.wait_group 2;" ::: "memory");
        else if (g + 1 < NGR) asm volatile("cp.async.wait_group 1;" ::: "memory");
        else                  asm volatile("cp.async.wait_group 0;" ::: "memory");
        __syncthreads();
        if (g + 3 < NGR) load_group(g + 3, (g + 3) % SSTG);

        const char* ub = ssm + s * GRP_BYTES;
        const char* xb = ub + GRP_U;
#pragma unroll
        for (int i = 0; i < SGS; i++) {
            const __half* up = (const __half*)(ub + i * 384) + 3 * tid;
            // half of (u + bias): gate = sigmoid(2*(hu + hb*c)) via tanh
            float hu0 = fmaf(0.5f, __half2float(up[0]), hb0);
            float hu1 = fmaf(0.5f, __half2float(up[1]), hb1);
            float u2  = __half2float(up[2]);
            float xv  = __half2float(*((const __half*)(xb + i * 128) + tid));

            // c' = u2 + f*(c-u2),  f = 0.5*th_f + 0.5
            float th_f = tanh_fast(fmaf(hb0, c, hu0));
            float d    = fmaf(0.5f, c, -0.5f * u2);
            c = fmaf(th_f, d, u2 + d);

            // h = x + r*(c'-x), r = 0.5*th_r + 0.5  (th_r from pre-update c)
            float th_r = tanh_fast(fmaf(hb1, d + d + u2, hu1)); // d+d+u2 == old c
            float e    = fmaf(0.5f, c, -0.5f * xv);
            float hv   = fmaf(th_r, e, xv + e);

            const size_t off = (size_t)(g * SGS + i) * XT;
            __stcs(hp + off, hv);
            __stcs(cp + off, c);
        }
    }
}

// ---------------------------------------------------------------------------
// Launch
// ---------------------------------------------------------------------------
extern "C" void kernel_launch(void* const* d_in, const int* in_sizes, int n_in,
                              void* d_out, int out_size)
{
    const float* input  = (const float*)d_in[0]; // [2048,16,1024]
    const float* weight = (const float*)d_in[1]; // [1024,3072]
    const float* bias   = (const float*)d_in[2]; // [2048]
    // d_in[3] = v, intentionally unused (source quirk)

    float* Hout = (float*)d_out;
    float* Cout = (float*)d_out + SBH;

    __half *U, *A, *B;
    cudaGetSymbolAddress((void**)&U, g_U);
    cudaGetSymbolAddress((void**)&A, g_A);
    cudaGetSymbolAddress((void**)&B, g_B);

    cudaFuncSetAttribute(gemm_fp16,
                         cudaFuncAttributeMaxDynamicSharedMemorySize, GEMM_SMEM);
    cudaFuncSetAttribute(sru_scan,
                         cudaFuncAttributeMaxDynamicSharedMemorySize, SCAN_SMEM);

    convA<<<SBH / 4 / 256, 256>>>((const float4*)input, (__half2*)A);
    convW<<<dim3(N3 / 32, KDIM / 32), dim3(32, 32)>>>(weight, B);

    gemm_fp16<<<dim3(N3 / 128, MROWS / 128), 128, GEMM_SMEM>>>(A, B, U);

    sru_scan<<<256, CH, SCAN_SMEM>>>(U, A, bias, Hout, Cout);
}

// round 14
// speedup vs baseline: 1.0232x; 1.0221x over previous
#include <cuda_runtime.h>
#include <cuda_fp16.h>
#include <cstdint>

// ---------------------------------------------------------------------------
// Problem constants
// ---------------------------------------------------------------------------
#define SEQ_LEN   2048
#define BATCH     16
#define HID       1024
#define N3        3072
#define KDIM      1024
#define MROWS     32768
#define SBH       (SEQ_LEN * BATCH * HID)  // 33554432

// Scratch (device globals; no runtime allocation allowed)
__device__ __half g_U[(size_t)MROWS * N3];    // GEMM output [M, 3H], fp16
__device__ __half g_A[(size_t)MROWS * KDIM];  // input fp16 [M,K] (= X in fp16)
__device__ __half g_B[(size_t)N3 * KDIM];     // weight^T fp16 [N,K]

// ---------------------------------------------------------------------------
// PTX helpers
// ---------------------------------------------------------------------------
__device__ __forceinline__ uint32_t smem_u32(const void* p) {
    uint32_t a;
    asm("{ .reg .u64 t; cvta.to.shared.u64 t, %1; cvt.u32.u64 %0, t; }"
        : "=r"(a) : "l"(p));
    return a;
}

__device__ __forceinline__ void cpasync16(uint32_t dst, const void* src) {
    asm volatile("cp.async.cg.shared.global [%0], [%1], 16;"
        :: "r"(dst), "l"(src) : "memory");
}

__device__ __forceinline__ void ldsm_x4(uint32_t r[4], uint32_t addr) {
    asm volatile("ldmatrix.sync.aligned.m8n8.x4.shared.b16 {%0,%1,%2,%3}, [%4];"
        : "=r"(r[0]), "=r"(r[1]), "=r"(r[2]), "=r"(r[3]) : "r"(addr));
}

__device__ __forceinline__ void mma16816(float* c, const uint32_t* a,
                                         uint32_t b0, uint32_t b1) {
    asm volatile(
        "mma.sync.aligned.m16n8k16.row.col.f32.f16.f16.f32 "
        "{%0,%1,%2,%3}, {%4,%5,%6,%7}, {%8,%9}, {%0,%1,%2,%3};"
        : "+f"(c[0]), "+f"(c[1]), "+f"(c[2]), "+f"(c[3])
        : "r"(a[0]), "r"(a[1]), "r"(a[2]), "r"(a[3]), "r"(b0), "r"(b1));
}

__device__ __forceinline__ float tanh_fast(float x) {
    float y;
    asm("tanh.approx.f32 %0, %1;" : "=f"(y) : "f"(x));
    return y;
}

__device__ __forceinline__ void stcs_half2(__half* p, __half2 v) {
    asm volatile("st.global.cs.b32 [%0], %1;" :: "l"(p), "r"(*(uint32_t*)&v) : "memory");
}

// ---------------------------------------------------------------------------
// Fused conversion kernel.
// Blocks [0, 32768): convA — X fp32 -> A fp16, 1024 floats per block.
// Blocks [32768, 32768+3072): convW — 32x32 transpose tiles of W -> B fp16.
//   convW tile index t in [0, 96*32): n-tile = t % 96, k-tile = t / 96.
// ---------------------------------------------------------------------------
#define CONVA_BLOCKS (SBH / 1024)        // 32768
#define CONVW_TILES  ((N3 / 32) * (KDIM / 32))  // 96*32 = 3072

__global__ void __launch_bounds__(256) conv_fused(
    const float4* __restrict__ X, __half2* __restrict__ A2,
    const float* __restrict__ W, __half* __restrict__ B)
{
    if (blockIdx.x < CONVA_BLOCKS) {
        size_t i = (size_t)blockIdx.x * 256 + threadIdx.x;
        float4 v = X[i];
        A2[2 * i]     = __floats2half2_rn(v.x, v.y);
        A2[2 * i + 1] = __floats2half2_rn(v.z, v.w);
    } else {
        __shared__ float t[32][33];
        int tile = blockIdx.x - CONVA_BLOCKS;
        int n0 = (tile % 96) * 32;
        int k0 = (tile / 96) * 32;
        int tx = threadIdx.x & 31;
        int ty4 = (threadIdx.x >> 5) * 4;       // 8 warps x 4 rows
#pragma unroll
        for (int r = 0; r < 4; r++)
            t[ty4 + r][tx] = W[(size_t)(k0 + ty4 + r) * N3 + n0 + tx];
        __syncthreads();
#pragma unroll
        for (int r = 0; r < 4; r++)
            B[(size_t)(n0 + ty4 + r) * KDIM + k0 + tx] =
                __float2half_rn(t[tx][ty4 + r]);
    }
}

// ---------------------------------------------------------------------------
// fp16 GEMM via mma.sync: U(fp16) = A*B^T (fp32 acc)  [R11 config, known-good]
// CTA tile 128x128, 4 warps of 64x64 (128 threads), 2 CTAs/SM.
// K-chunk 64, SW128 smem, 3-stage single-sync ring. Streaming epilogue.
// ---------------------------------------------------------------------------
#define TKC 64
#define NCHUNK (KDIM / TKC)          // 16
#define TILE_BYTES 16384             // 128 rows x 128B
#define STAGE_BYTES (2 * TILE_BYTES) // A + B = 32KB
#define NSTAGE 3
#define GEMM_SMEM (1024 + NSTAGE * STAGE_BYTES)

__global__ void __launch_bounds__(128, 2) gemm_fp16(
    const __half* __restrict__ A, const __half* __restrict__ B,
    __half* __restrict__ U)
{
    extern __shared__ char dsm[];
    const uint32_t base = (smem_u32(dsm) + 1023) & ~1023u;

    const int tid = threadIdx.x;
    const int wid = tid >> 5, lid = tid & 31;
    const int m0 = blockIdx.y * 128;
    const int n0 = blockIdx.x * 128;
    const int wm = (wid & 1) * 64;     // warp M offset (0 or 64)
    const int wn = (wid >> 1) * 64;    // warp N offset (0 or 64)

    // loader: 128 threads cover A (8 chunks) + B (8 chunks) of 16B each
    auto load_chunk = [&](int j, int s) {
        const uint32_t sb = base + s * STAGE_BYTES;
        const int koff = j * TKC;
#pragma unroll
        for (int i = 0; i < 8; i++) {
            int q = i * 128 + tid;
            int r = q >> 3, c = q & 7;
            uint32_t sw = (uint32_t)(r * 128 + ((c * 16) ^ ((r & 7) << 4)));
            cpasync16(sb + sw,              A + (size_t)(m0 + r) * KDIM + koff + c * 8);
            cpasync16(sb + TILE_BYTES + sw, B + (size_t)(n0 + r) * KDIM + koff + c * 8);
        }
        asm volatile("cp.async.commit_group;" ::: "memory");
    };

    const int fr = lid & 15;
    const int fc = lid >> 4;
    const uint32_t axor = (uint32_t)((fr & 7) << 4);

    float acc[4][8][4];
#pragma unroll
    for (int a = 0; a < 4; a++)
#pragma unroll
        for (int b = 0; b < 8; b++)
#pragma unroll
            for (int q = 0; q < 4; q++) acc[a][b][q] = 0.0f;

    load_chunk(0, 0);
    load_chunk(1, 1);

    for (int j = 0; j < NCHUNK; j++) {
        const int s = j % NSTAGE;
        if (j + 1 < NCHUNK) asm volatile("cp.async.wait_group 1;" ::: "memory");
        else                asm volatile("cp.async.wait_group 0;" ::: "memory");
        __syncthreads();
        // stage (j+2)%3 == (j-1)%3 was consumed at iter j-1; the sync above
        // makes that consumption block-wide complete before we overwrite it.
        if (j + 2 < NCHUNK) load_chunk(j + 2, (j + 2) % NSTAGE);

        const uint32_t As = base + s * STAGE_BYTES;
        const uint32_t Bs = As + TILE_BYTES;

#pragma unroll
        for (int ks = 0; ks < 4; ks++) {
            const uint32_t kb = (uint32_t)(ks * 32 + fc * 16) ^ axor;

            uint32_t afr[4][4];
#pragma unroll
            for (int mi = 0; mi < 4; mi++)
                ldsm_x4(afr[mi], As + (uint32_t)((wm + mi * 16 + fr) * 128) + kb);

            uint32_t bfr[4][4];
#pragma unroll
            for (int nj = 0; nj < 4; nj++)
                ldsm_x4(bfr[nj], Bs + (uint32_t)((wn + nj * 16 + fr) * 128) + kb);

#pragma unroll
            for (int mi = 0; mi < 4; mi++)
#pragma unroll
                for (int n8 = 0; n8 < 8; n8++)
                    mma16816(acc[mi][n8], afr[mi],
                             bfr[n8 >> 1][n8 & 1], bfr[n8 >> 1][(n8 & 1) + 2]);
        }
    }

    // epilogue: fp32 acc -> fp16 U, streaming stores
    const int crow = lid >> 2;
    const int ccol = (lid & 3) * 2;
#pragma unroll
    for (int mi = 0; mi < 4; mi++) {
#pragma unroll
        for (int n8 = 0; n8 < 8; n8++) {
            __half* p0 = U + (size_t)(m0 + wm + mi * 16 + crow) * N3
                           + n0 + wn + n8 * 8 + ccol;
            __half* p1 = p0 + (size_t)8 * N3;
            stcs_half2(p0, __floats2half2_rn(acc[mi][n8][0], acc[mi][n8][1]));
            stcs_half2(p1, __floats2half2_rn(acc[mi][n8][2], acc[mi][n8][3]));
        }
    }
}

// ---------------------------------------------------------------------------
// SRU scan with cp.async smem staging + tanh.approx gates. [R11, known-good]
// Block = 128 threads = 128 h-chains; groups of 32 timesteps, 4-stage ring.
// ---------------------------------------------------------------------------
#define SGS 32
#define GRP_U (SGS * 768)            // 24576
#define GRP_X (SGS * 256)            // 8192
#define GRP_BYTES (GRP_U + GRP_X)    // 32768
#define NGR (SEQ_LEN / SGS)          // 64
#define SSTG 4
#define SCAN_SMEM (SSTG * GRP_BYTES) // 131072

__global__ void __launch_bounds__(128) sru_scan(
    const __half* __restrict__ Uh, const __half* __restrict__ Xh,
    const float* __restrict__ bias,
    float* __restrict__ Hout, float* __restrict__ Cout)
{
    extern __shared__ char ssm[];
    const uint32_t sbase = smem_u32(ssm);
    const int tid = threadIdx.x;
    const int b   = blockIdx.x >> 3;
    const int hb  = blockIdx.x & 7;
    const int h   = hb * 128 + tid;

    const float b0 = bias[h];
    const float b1 = bias[HID + h];
    const float hb0 = 0.5f * b0;   // gate arg scaled by 1/2 for tanh identity
    const float hb1 = 0.5f * b1;

    // loader chunk geometry: U 12 chunks, X 4 chunks of 16B per thread
    int us[12], uc[12], xs[4], xc[4];
#pragma unroll
    for (int k = 0; k < 12; k++) { int q = tid + 128 * k; us[k] = q / 48; uc[k] = q % 48; }
#pragma unroll
    for (int k = 0; k < 4; k++)  { int q = tid + 128 * k; xs[k] = q >> 4; xc[k] = q & 15; }

    const size_t UT = (size_t)BATCH * N3;    // halves per timestep in U
    const size_t XT = (size_t)BATCH * HID;   // elems per timestep in X / outputs

    const __half* Ublk = Uh + (size_t)b * N3 + hb * 384;
    const __half* Xblk = Xh + (size_t)b * HID + hb * 128;

    auto load_group = [&](int g, int s) {
        const uint32_t sb = sbase + s * GRP_BYTES;
        const __half* Ug = Ublk + (size_t)g * SGS * UT;
        const __half* Xg = Xblk + (size_t)g * SGS * XT;
#pragma unroll
        for (int k = 0; k < 12; k++)
            cpasync16(sb + us[k] * 768 + uc[k] * 16,
                      Ug + (size_t)us[k] * UT + uc[k] * 8);
#pragma unroll
        for (int k = 0; k < 4; k++)
            cpasync16(sb + GRP_U + xs[k] * 256 + xc[k] * 16,
                      Xg + (size_t)xs[k] * XT + xc[k] * 8);
        asm volatile("cp.async.commit_group;" ::: "memory");
    };

    load_group(0, 0);
    load_group(1, 1);
    load_group(2, 2);

    float c = 0.0f;
    float* hp = Hout + (size_t)b * HID + h;
    float* cp = Cout + (size_t)b * HID + h;

    for (int g = 0; g < NGR; g++) {
        const int s = g % SSTG;
        if (g + 2 < NGR)      asm volatile("cp.async.wait_group 2;" ::: "memory");
        else if (g + 1 < NGR) asm volatile("cp.async.wait_group 1;" ::: "memory");
        else                  asm volatile("cp.async.wait_group 0;" ::: "memory");
        __syncthreads();
        if (g + 3 < NGR) load_group(g + 3, (g + 3) % SSTG);

        const char* ub = ssm + s * GRP_BYTES;
        const char* xb = ub + GRP_U;
#pragma unroll
        for (int i = 0; i < SGS; i++) {
            const __half* up = (const __half*)(ub + i * 768) + 3 * tid;
            // half of (u + bias): gate = sigmoid(2*(hu + hb*c)) via tanh
            float hu0 = fmaf(0.5f, __half2float(up[0]), hb0);
            float hu1 = fmaf(0.5f, __half2float(up[1]), hb1);
            float u2  = __half2float(up[2]);
            float xv  = __half2float(*((const __half*)(xb + i * 256) + tid));

            // c' = u2 + f*(c-u2),  f = 0.5*th_f + 0.5
            float th_f = tanh_fast(fmaf(hb0, c, hu0));
            float d    = fmaf(0.5f, c, -0.5f * u2);
            c = fmaf(th_f, d, u2 + d);

            // h = x + r*(c'-x), r = 0.5*th_r + 0.5  (th_r from pre-update c)
            float th_r = tanh_fast(fmaf(hb1, d + d + u2, hu1)); // d+d+u2 == old c
            float e    = fmaf(0.5f, c, -0.5f * xv);
            float hv   = fmaf(th_r, e, xv + e);

            const size_t off = (size_t)(g * SGS + i) * XT;
            __stcs(hp + off, hv);
            __stcs(cp + off, c);
        }
    }
}

// ---------------------------------------------------------------------------
// Launch
// ---------------------------------------------------------------------------
extern "C" void kernel_launch(void* const* d_in, const int* in_sizes, int n_in,
                              void* d_out, int out_size)
{
    const float* input  = (const float*)d_in[0]; // [2048,16,1024]
    const float* weight = (const float*)d_in[1]; // [1024,3072]
    const float* bias   = (const float*)d_in[2]; // [2048]
    // d_in[3] = v, intentionally unused (source quirk)

    float* Hout = (float*)d_out;
    float* Cout = (float*)d_out + SBH;

    __half *U, *A, *B;
    cudaGetSymbolAddress((void**)&U, g_U);
    cudaGetSymbolAddress((void**)&A, g_A);
    cudaGetSymbolAddress((void**)&B, g_B);

    cudaFuncSetAttribute(gemm_fp16,
                         cudaFuncAttributeMaxDynamicSharedMemorySize, GEMM_SMEM);
    cudaFuncSetAttribute(sru_scan,
                         cudaFuncAttributeMaxDynamicSharedMemorySize, SCAN_SMEM);

    conv_fused<<<CONVA_BLOCKS + CONVW_TILES, 256>>>(
        (const float4*)input, (__half2*)A, weight, B);

    gemm_fp16<<<dim3(N3 / 128, MROWS / 128), 128, GEMM_SMEM>>>(A, B, U);

    sru_scan<<<128, 128, SCAN_SMEM>>>(U, A, bias, Hout, Cout);
}